// round 11
// baseline (speedup 1.0000x reference)
#include <cuda_runtime.h>
#include <math.h>
#include <stdint.h>

// ---------------- problem constants ----------------
#define NN   10000
#define EE   160000
#define ET   (EE + NN)      // edges + self loops
#define FIN  256
#define HID  128
#define H1N  5
#define H3N  3
#define D1   (H1N * HID)    // 640
#define D3   (H3N * HID)    // 384
#define GG   64
#define NCLS 10

// ---------------- device scratch (static globals: no allocation) ----------------
__device__ float g_h [NN * D1];
__device__ float g_x1[NN * D1];
__device__ float g_x2[NN * D1];
__device__ float g_als[NN * H1N];
__device__ float g_ald[NN * H1N];
__device__ float g_Wt1[FIN * D1];
__device__ float g_Wt2[D1 * D1];
__device__ float g_Wt3[D1 * D3];
__device__ int   g_deg[NN];
__device__ int   g_offs[NN + 1];
__device__ int   g_cur[NN];
__device__ int   g_csr[ET];
__device__ float g_pooled[GG * HID];
__device__ int   g_cnt[GG];

__device__ __forceinline__ uint32_t to_tf32(float x) {
    uint32_t u;
    asm("cvt.rna.tf32.f32 %0, %1;" : "=r"(u) : "f"(x));
    return u;
}

// ---------------- CSR build ----------------
__global__ void k_zero() {
    int i = blockIdx.x * blockDim.x + threadIdx.x;
    if (i < NN) g_deg[i] = 0;
    if (i < GG * HID) g_pooled[i] = 0.f;
    if (i < GG) g_cnt[i] = 0;
}

__global__ void k_count(const int* __restrict__ ei) {
    int e = blockIdx.x * blockDim.x + threadIdx.x;
    if (e >= ET) return;
    int dst = (e < EE) ? ei[EE + e] : (e - EE);
    atomicAdd(&g_deg[dst], 1);
}

__global__ void k_scan() {
    __shared__ int sh[1024];
    __shared__ int carry;
    int tid = threadIdx.x;
    if (tid == 0) carry = 0;
    __syncthreads();
    for (int base = 0; base < NN; base += 1024) {
        int i = base + tid;
        int v = (i < NN) ? g_deg[i] : 0;
        sh[tid] = v;
        __syncthreads();
        for (int off = 1; off < 1024; off <<= 1) {
            int t = (tid >= off) ? sh[tid - off] : 0;
            __syncthreads();
            sh[tid] += t;
            __syncthreads();
        }
        int excl = sh[tid] - v + carry;
        if (i < NN) { g_offs[i] = excl; g_cur[i] = excl; }
        __syncthreads();
        if (tid == 1023) carry += sh[1023];
        __syncthreads();
    }
    if (tid == 0) g_offs[NN] = carry;
}

__global__ void k_scatter(const int* __restrict__ ei) {
    int e = blockIdx.x * blockDim.x + threadIdx.x;
    if (e >= ET) return;
    int src, dst;
    if (e < EE) { src = ei[e]; dst = ei[EE + e]; }
    else        { src = dst = e - EE; }
    int pos = atomicAdd(&g_cur[dst], 1);
    g_csr[pos] = src;
}

// ---------------- weight transpose (+tf32 rounding): Wt[n][k] = tf32(W[k][n]) ----------------
__global__ void k_transpose(const float* __restrict__ W, float* __restrict__ Wt,
                            int K, int N) {
    __shared__ float t[32][33];
    int nb = blockIdx.x * 32, kb = blockIdx.y * 32;
    int x = threadIdx.x, y = threadIdx.y;
#pragma unroll
    for (int i = 0; i < 32; i += 8) {
        int k = kb + y + i, n = nb + x;
        t[y + i][x] = (k < K && n < N) ? W[(size_t)k * N + n] : 0.f;
    }
    __syncthreads();
#pragma unroll
    for (int i = 0; i < 32; i += 8) {
        int n = nb + y + i, k = kb + x;
        if (n < N && k < K)
            Wt[(size_t)n * K + k] = __uint_as_float(to_tf32(t[x][y + i]));
    }
}

// ---------------- tf32 mma.sync GEMM + fused attention logits ----------------
// Block tile 128x128, BK=16. 256 threads = 8 warps (4x2), warp tile 32x64.
// Fragment loads via ldmatrix.m8n8.x4 (8x4 tf32 tile viewed as 8x8 b16).
#define SAPITCH 20   // 16 + 4 pad (floats)

__device__ __forceinline__ void mma_tf32(float* c, const uint32_t* a, const uint32_t* b) {
    asm volatile(
        "mma.sync.aligned.m16n8k8.row.col.f32.tf32.tf32.f32 "
        "{%0,%1,%2,%3}, {%4,%5,%6,%7}, {%8,%9}, {%0,%1,%2,%3};"
        : "+f"(c[0]), "+f"(c[1]), "+f"(c[2]), "+f"(c[3])
        : "r"(a[0]), "r"(a[1]), "r"(a[2]), "r"(a[3]), "r"(b[0]), "r"(b[1]));
}

__device__ __forceinline__ void ldsm_x4(uint32_t& r0, uint32_t& r1,
                                        uint32_t& r2, uint32_t& r3, uint32_t sa) {
    asm volatile("ldmatrix.sync.aligned.m8n8.x4.shared.b16 {%0,%1,%2,%3}, [%4];"
                 : "=r"(r0), "=r"(r1), "=r"(r2), "=r"(r3) : "r"(sa));
}

__global__ __launch_bounds__(256, 2)
void k_tc_gemm(const float* __restrict__ A, const float* __restrict__ Bt,
               float* __restrict__ C,
               const float* __restrict__ asrc, const float* __restrict__ adst,
               float* __restrict__ als, float* __restrict__ ald,
               int H, int M, int Nmat, int K)
{
    __shared__ uint32_t sA[128 * SAPITCH];
    __shared__ uint32_t sB[128 * SAPITCH];
    __shared__ float s_als[128];
    __shared__ float s_ald[128];

    int tid  = threadIdx.x;
    int lane = tid & 31;
    int warp = tid >> 5;
    int warpM = warp >> 1;          // 0..3
    int warpN = warp & 1;           // 0..1
    int g = lane >> 2;              // 0..7
    int t = lane & 3;               // 0..3

    int rowBase = blockIdx.y * 128;
    int colBase = blockIdx.x * 128;

    if (tid < 128) { s_als[tid] = 0.f; s_ald[tid] = 0.f; }

    // ldmatrix per-lane address bases (byte offsets into shared)
    // A call (mt, ks): lane i -> row warpM*32 + mt*16 + ((i>>3)&1)*8 + (i&7), col ks + (i>>4)*4
    // B call (np, ks): lane i -> row warpN*64 + np*16 + (i>>4)*8 + (i&7),     col ks + ((i>>3)&1)*4
    uint32_t sAu = (uint32_t)__cvta_generic_to_shared(sA);
    uint32_t sBu = (uint32_t)__cvta_generic_to_shared(sB);
    uint32_t aAddr = sAu + (((warpM * 32 + ((lane >> 3) & 1) * 8 + (lane & 7)) * SAPITCH
                             + (lane >> 4) * 4) << 2);
    uint32_t bAddr = sBu + (((warpN * 64 + (lane >> 4) * 8 + (lane & 7)) * SAPITCH
                             + ((lane >> 3) & 1) * 4) << 2);

    float acc[2][8][4];
#pragma unroll
    for (int i = 0; i < 2; i++)
#pragma unroll
        for (int j = 0; j < 8; j++)
#pragma unroll
            for (int q = 0; q < 4; q++) acc[i][j][q] = 0.f;

    float4 pa[2], pb[2];

#define FETCH_TILE(k0)                                                         \
    {                                                                          \
        _Pragma("unroll")                                                      \
        for (int i = 0; i < 2; i++) {                                          \
            int idx = tid + i * 256;                                           \
            int r = idx >> 2, c = (idx & 3) * 4;                               \
            int gr = rowBase + r;                                              \
            pa[i] = make_float4(0.f, 0.f, 0.f, 0.f);                           \
            if (gr < M) pa[i] = *(const float4*)(A + (size_t)gr * K + (k0) + c); \
            pb[i] = *(const float4*)(Bt + (size_t)(colBase + r) * K + (k0) + c); \
        }                                                                      \
    }

#define STORE_TILE()                                                           \
    {                                                                          \
        _Pragma("unroll")                                                      \
        for (int i = 0; i < 2; i++) {                                          \
            int idx = tid + i * 256;                                           \
            int r = idx >> 2, c = (idx & 3) * 4;                               \
            uint32_t* ap = &sA[r * SAPITCH + c];                               \
            ap[0] = to_tf32(pa[i].x); ap[1] = to_tf32(pa[i].y);                \
            ap[2] = to_tf32(pa[i].z); ap[3] = to_tf32(pa[i].w);                \
            uint32_t* bp = &sB[r * SAPITCH + c];                               \
            bp[0] = __float_as_uint(pb[i].x); bp[1] = __float_as_uint(pb[i].y);\
            bp[2] = __float_as_uint(pb[i].z); bp[3] = __float_as_uint(pb[i].w);\
        }                                                                      \
    }

    FETCH_TILE(0);
    STORE_TILE();
    __syncthreads();

    int iters = K >> 4;
    for (int it = 0; it < iters; it++) {
        if (it + 1 < iters) FETCH_TILE((it + 1) << 4);

#pragma unroll
        for (int ks = 0; ks < 16; ks += 8) {
            uint32_t a[2][4], b[8][2];
#pragma unroll
            for (int mt = 0; mt < 2; mt++)      // A: 2 ldmatrix.x4
                ldsm_x4(a[mt][0], a[mt][1], a[mt][2], a[mt][3],
                        aAddr + ((mt * 16 * SAPITCH + ks) << 2));
#pragma unroll
            for (int np = 0; np < 4; np++)      // B: 4 ldmatrix.x4 (2 n-tiles each)
                ldsm_x4(b[2 * np][0], b[2 * np][1], b[2 * np + 1][0], b[2 * np + 1][1],
                        bAddr + ((np * 16 * SAPITCH + ks) << 2));
#pragma unroll
            for (int mt = 0; mt < 2; mt++)
#pragma unroll
                for (int nt = 0; nt < 8; nt++)
                    mma_tf32(acc[mt][nt], a[mt], b[nt]);
        }

        __syncthreads();
        if (it + 1 < iters) {
            STORE_TILE();
            __syncthreads();
        }
    }

    // ---- C store ----
#pragma unroll
    for (int mt = 0; mt < 2; mt++) {
        int row = rowBase + warpM * 32 + mt * 16 + g;
#pragma unroll
        for (int nt = 0; nt < 8; nt++) {
            int col = colBase + warpN * 64 + nt * 8 + 2 * t;
            if (row < M)
                *(float2*)(C + (size_t)row * Nmat + col) =
                    make_float2(acc[mt][nt][0], acc[mt][nt][1]);
            if (row + 8 < M)
                *(float2*)(C + (size_t)(row + 8) * Nmat + col) =
                    make_float2(acc[mt][nt][2], acc[mt][nt][3]);
        }
    }

    // ---- fused attn logits: als/ald for this (row block, head) ----
    {
        int hd = blockIdx.x;                        // colBase / 128
        const float* as = asrc + hd * HID;
        const float* ad = adst + hd * HID;
#pragma unroll
        for (int mt = 0; mt < 2; mt++) {
            float ps0 = 0.f, pd0 = 0.f, ps1 = 0.f, pd1 = 0.f;
#pragma unroll
            for (int nt = 0; nt < 8; nt++) {
                int cih = warpN * 64 + nt * 8 + 2 * t;
                float a0 = as[cih], a1 = as[cih + 1];
                float d0 = ad[cih], d1 = ad[cih + 1];
                ps0 += acc[mt][nt][0] * a0 + acc[mt][nt][1] * a1;
                pd0 += acc[mt][nt][0] * d0 + acc[mt][nt][1] * d1;
                ps1 += acc[mt][nt][2] * a0 + acc[mt][nt][3] * a1;
                pd1 += acc[mt][nt][2] * d0 + acc[mt][nt][3] * d1;
            }
            int rl = warpM * 32 + mt * 16 + g;
            atomicAdd(&s_als[rl], ps0);     atomicAdd(&s_ald[rl], pd0);
            atomicAdd(&s_als[rl + 8], ps1); atomicAdd(&s_ald[rl + 8], pd1);
        }
        __syncthreads();
        if (tid < 128) {
            int row = rowBase + tid;
            if (row < M) {
                als[row * H + hd] = s_als[tid];
                ald[row * H + hd] = s_ald[tid];
            }
        }
    }
#undef FETCH_TILE
#undef STORE_TILE
}

// ---------------- fused edge-softmax + aggregate: block=node, warp=head ----------------
__device__ __forceinline__ float leaky02(float x) { return x > 0.f ? x : 0.2f * x; }
__device__ __forceinline__ float eluf(float x)    { return x > 0.f ? x : expm1f(x); }

__device__ __forceinline__ float4 agg_head(const float* __restrict__ h,
                                           const float* __restrict__ als,
                                           float ald, int hd, int H, int D,
                                           int start, int end, int lane)
{
    // pass 1: warp-level max & expsum
    float m = -1e30f;
    for (int i = start + lane; i < end; i += 32)
        m = fmaxf(m, leaky02(als[g_csr[i] * H + hd] + ald));
#pragma unroll
    for (int o = 16; o > 0; o >>= 1) m = fmaxf(m, __shfl_xor_sync(0xffffffffu, m, o));
    float ssum = 0.f;
    for (int i = start + lane; i < end; i += 32)
        ssum += __expf(leaky02(als[g_csr[i] * H + hd] + ald) - m);
#pragma unroll
    for (int o = 16; o > 0; o >>= 1) ssum += __shfl_xor_sync(0xffffffffu, ssum, o);
    float inv = 1.f / (ssum + 1e-16f);

    // pass 2: weighted float4 gather; weights/srcs broadcast via shfl
    float4 acc = make_float4(0.f, 0.f, 0.f, 0.f);
    const float4* h4 = (const float4*)h;
    int rowStride = D >> 2;
    int colOff = hd * 32 + lane;
    for (int base = start; base < end; base += 32) {
        int e = base + lane;
        int s = 0; float w = 0.f;
        if (e < end) {
            s = g_csr[e];
            w = __expf(leaky02(als[s * H + hd] + ald) - m) * inv;
        }
        int cnt = min(32, end - base);
#pragma unroll 4
        for (int j = 0; j < cnt; j++) {
            int   sj = __shfl_sync(0xffffffffu, s, j);
            float wj = __shfl_sync(0xffffffffu, w, j);
            float4 v = h4[(size_t)sj * rowStride + colOff];
            acc.x += wj * v.x; acc.y += wj * v.y;
            acc.z += wj * v.z; acc.w += wj * v.w;
        }
    }
    return acc;
}

// MODE 1: out = elu(acc + bias); MODE 2: out = elu(resid + acc + bias)
template <int MODE>
__global__ void k_agg(const float* __restrict__ h, const float* __restrict__ als,
                      const float* __restrict__ aldp, const float* __restrict__ bias,
                      const float* __restrict__ resid, float* __restrict__ out,
                      int H, int D)
{
    int node = blockIdx.x;
    int hd   = threadIdx.y;
    int lane = threadIdx.x;
    int start = g_offs[node], end = g_offs[node + 1];
    float ald = aldp[node * H + hd];

    float4 acc = agg_head(h, als, ald, hd, H, D, start, end, lane);

    int col = hd * HID + lane * 4;
    const float4 b = *(const float4*)(bias + col);
    float4 o_;
    if (MODE == 1) {
        o_.x = eluf(acc.x + b.x); o_.y = eluf(acc.y + b.y);
        o_.z = eluf(acc.z + b.z); o_.w = eluf(acc.w + b.w);
    } else {
        const float4 r = *(const float4*)(resid + (size_t)node * D + col);
        o_.x = eluf(acc.x + b.x + r.x); o_.y = eluf(acc.y + b.y + r.y);
        o_.z = eluf(acc.z + b.z + r.z); o_.w = eluf(acc.w + b.w + r.w);
    }
    *(float4*)(out + (size_t)node * D + col) = o_;
}

// Layer-3 agg fused with head-mean + bias + global mean pool (atomic into g_pooled)
__global__ void k_agg3(const float* __restrict__ h, const float* __restrict__ als,
                       const float* __restrict__ aldp, const float* __restrict__ b3,
                       const int* __restrict__ batch)
{
    __shared__ float4 sacc[H3N][32];

    int node = blockIdx.x;
    int hd   = threadIdx.y;
    int lane = threadIdx.x;
    int start = g_offs[node], end = g_offs[node + 1];
    float ald = aldp[node * H3N + hd];

    float4 acc = agg_head(h, als, ald, hd, H3N, D3, start, end, lane);
    sacc[hd][lane] = acc;
    __syncthreads();

    if (hd == 0) {
        float4 a0 = sacc[0][lane], a1 = sacc[1][lane], a2 = sacc[2][lane];
        const float4 b = *(const float4*)(b3 + lane * 4);
        float4 v;
        v.x = (a0.x + a1.x + a2.x) * (1.f / 3.f) + b.x;
        v.y = (a0.y + a1.y + a2.y) * (1.f / 3.f) + b.y;
        v.z = (a0.z + a1.z + a2.z) * (1.f / 3.f) + b.z;
        v.w = (a0.w + a1.w + a2.w) * (1.f / 3.f) + b.w;
        int grp = batch[node];
        float* pp = g_pooled + grp * HID + lane * 4;
        atomicAdd(pp + 0, v.x);
        atomicAdd(pp + 1, v.y);
        atomicAdd(pp + 2, v.z);
        atomicAdd(pp + 3, v.w);
        if (lane == 0) atomicAdd(&g_cnt[grp], 1);
    }
}

__global__ void k_classify(const float* __restrict__ Wc, const float* __restrict__ bc,
                           float* __restrict__ out, int out_size)
{
    __shared__ float lg[GG * NCLS];
    __shared__ float rowm[GG], rowl[GG];
    int t = threadIdx.x;            // 640 threads
    int g = t / NCLS, c = t - g * NCLS;
    float cnt = (float)max(g_cnt[g], 1);
    float s = 0.f;
#pragma unroll
    for (int k = 0; k < HID; k++) s += g_pooled[g * HID + k] * Wc[k * NCLS + c];
    float logit = s / cnt + bc[c];
    lg[t] = logit;
    __syncthreads();
    if (t < GG) {
        float m = -1e30f;
        for (int j = 0; j < NCLS; j++) m = fmaxf(m, lg[t * NCLS + j]);
        float se = 0.f;
        for (int j = 0; j < NCLS; j++) se += expf(lg[t * NCLS + j] - m);
        rowm[t] = m; rowl[t] = logf(se);
    }
    __syncthreads();
    out[t] = logit;
    if (out_size >= 2 * GG * NCLS)
        out[GG * NCLS + t] = logit - rowm[g] - rowl[g];
}

// ---------------- launch ----------------
extern "C" void kernel_launch(void* const* d_in, const int* in_sizes, int n_in,
                              void* d_out, int out_size)
{
    const float* x     = (const float*)d_in[0];
    const int*   ei    = (const int*)  d_in[1];
    const int*   batch = (const int*)  d_in[2];
    const float* W1  = (const float*)d_in[3];
    const float* a1s = (const float*)d_in[4];
    const float* a1d = (const float*)d_in[5];
    const float* b1  = (const float*)d_in[6];
    const float* W2  = (const float*)d_in[7];
    const float* a2s = (const float*)d_in[8];
    const float* a2d = (const float*)d_in[9];
    const float* b2  = (const float*)d_in[10];
    const float* W3  = (const float*)d_in[11];
    const float* a3s = (const float*)d_in[12];
    const float* a3d = (const float*)d_in[13];
    const float* b3  = (const float*)d_in[14];
    const float* Wc  = (const float*)d_in[15];
    const float* bc  = (const float*)d_in[16];
    float* out = (float*)d_out;

    float *h_, *x1_, *x2_, *als_, *ald_, *wt1_, *wt2_, *wt3_;
    cudaGetSymbolAddress((void**)&h_,  g_h);
    cudaGetSymbolAddress((void**)&x1_, g_x1);
    cudaGetSymbolAddress((void**)&x2_, g_x2);
    cudaGetSymbolAddress((void**)&als_, g_als);
    cudaGetSymbolAddress((void**)&ald_, g_ald);
    cudaGetSymbolAddress((void**)&wt1_, g_Wt1);
    cudaGetSymbolAddress((void**)&wt2_, g_Wt2);
    cudaGetSymbolAddress((void**)&wt3_, g_Wt3);

    dim3 tb(32, 8);

    // Hoisted transposes — keep gemm1 at launch index 3 (profiled slot).
    k_transpose<<<dim3(D1 / 32, FIN / 32), tb>>>(W1, wt1_, FIN, D1);   // 0
    k_transpose<<<dim3(D1 / 32, D1 / 32), tb>>>(W2, wt2_, D1, D1);     // 1
    k_transpose<<<dim3(D3 / 32, D1 / 32), tb>>>(W3, wt3_, D1, D3);     // 2

    // Layer-1 GEMM (+fused attn)                                      // 3
    k_tc_gemm<<<dim3(D1 / 128, (NN + 127) / 128), 256>>>(
        x, wt1_, h_, a1s, a1d, als_, ald_, H1N, NN, D1, FIN);

    // CSR by dst
    k_zero   <<<(NN + 255) / 256, 256>>>();           // 4
    k_count  <<<(ET + 255) / 256, 256>>>(ei);         // 5
    k_scan   <<<1, 1024>>>();                         // 6
    k_scatter<<<(ET + 255) / 256, 256>>>(ei);         // 7

    // Layer 1 aggregate
    k_agg<1><<<NN, dim3(32, H1N)>>>(h_, als_, ald_, b1, nullptr, x1_, H1N, D1);

    // Layer 2 (residual)
    k_tc_gemm<<<dim3(D1 / 128, (NN + 127) / 128), 256>>>(
        x1_, wt2_, h_, a2s, a2d, als_, ald_, H1N, NN, D1, D1);
    k_agg<2><<<NN, dim3(32, H1N)>>>(h_, als_, ald_, b2, x1_, x2_, H1N, D1);

    // Layer 3 (head mean + pool fused)
    k_tc_gemm<<<dim3(D3 / 128, (NN + 127) / 128), 256>>>(
        x2_, wt3_, h_, a3s, a3d, als_, ald_, H3N, NN, D3, D1);
    k_agg3<<<NN, dim3(32, H3N)>>>(h_, als_, ald_, b3, batch);

    // Classify
    k_classify<<<1, GG * NCLS>>>(Wc, bc, out, out_size);
}

// round 14
// speedup vs baseline: 1.5562x; 1.5562x over previous
#include <cuda_runtime.h>
#include <math.h>
#include <stdint.h>

// ---------------- problem constants ----------------
#define NN   10000
#define EE   160000
#define ET   (EE + NN)      // edges + self loops
#define FIN  256
#define HID  128
#define H1N  5
#define H3N  3
#define D1   (H1N * HID)    // 640
#define D3   (H3N * HID)    // 384
#define GG   64
#define NCLS 10

// ---------------- device scratch (static globals: no allocation) ----------------
__device__ float g_h [NN * D1];
__device__ float g_x1[NN * D1];
__device__ float g_x2[NN * D1];      // also reused as rounded-x scratch for GEMM1
__device__ float g_als[NN * H1N];
__device__ float g_ald[NN * H1N];
__device__ float g_Wt1[FIN * D1];
__device__ float g_Wt2[D1 * D1];
__device__ float g_Wt3[D1 * D3];
__device__ int   g_deg[NN];
__device__ int   g_offs[NN + 1];
__device__ int   g_cur[NN];
__device__ int   g_csr[ET];
__device__ float g_pooled[GG * HID];
__device__ int   g_cnt[GG];

__device__ __forceinline__ uint32_t to_tf32(float x) {
    uint32_t u;
    asm("cvt.rna.tf32.f32 %0, %1;" : "=r"(u) : "f"(x));
    return u;
}

// ---------------- CSR build ----------------
__global__ void k_zero() {
    int i = blockIdx.x * blockDim.x + threadIdx.x;
    if (i < NN) g_deg[i] = 0;
    if (i < GG * HID) g_pooled[i] = 0.f;
    if (i < GG) g_cnt[i] = 0;
}

__global__ void k_count(const int* __restrict__ ei) {
    int e = blockIdx.x * blockDim.x + threadIdx.x;
    if (e >= ET) return;
    int dst = (e < EE) ? ei[EE + e] : (e - EE);
    atomicAdd(&g_deg[dst], 1);
}

__global__ void k_scan() {
    __shared__ int sh[1024];
    __shared__ int carry;
    int tid = threadIdx.x;
    if (tid == 0) carry = 0;
    __syncthreads();
    for (int base = 0; base < NN; base += 1024) {
        int i = base + tid;
        int v = (i < NN) ? g_deg[i] : 0;
        sh[tid] = v;
        __syncthreads();
        for (int off = 1; off < 1024; off <<= 1) {
            int t = (tid >= off) ? sh[tid - off] : 0;
            __syncthreads();
            sh[tid] += t;
            __syncthreads();
        }
        int excl = sh[tid] - v + carry;
        if (i < NN) { g_offs[i] = excl; g_cur[i] = excl; }
        __syncthreads();
        if (tid == 1023) carry += sh[1023];
        __syncthreads();
    }
    if (tid == 0) g_offs[NN] = carry;
}

__global__ void k_scatter(const int* __restrict__ ei) {
    int e = blockIdx.x * blockDim.x + threadIdx.x;
    if (e >= ET) return;
    int src, dst;
    if (e < EE) { src = ei[e]; dst = ei[EE + e]; }
    else        { src = dst = e - EE; }
    int pos = atomicAdd(&g_cur[dst], 1);
    g_csr[pos] = src;
}

// ---------------- weight transpose (+tf32 rounding): Wt[n][k] = tf32(W[k][n]) ----------------
__global__ void k_transpose(const float* __restrict__ W, float* __restrict__ Wt,
                            int K, int N) {
    __shared__ float t[32][33];
    int nb = blockIdx.x * 32, kb = blockIdx.y * 32;
    int x = threadIdx.x, y = threadIdx.y;
#pragma unroll
    for (int i = 0; i < 32; i += 8) {
        int k = kb + y + i, n = nb + x;
        t[y + i][x] = (k < K && n < N) ? W[(size_t)k * N + n] : 0.f;
    }
    __syncthreads();
#pragma unroll
    for (int i = 0; i < 32; i += 8) {
        int n = nb + y + i, k = kb + x;
        if (n < N && k < K)
            Wt[(size_t)n * K + k] = __uint_as_float(to_tf32(t[x][y + i]));
    }
}

// ---------------- tf32 rounding pass (for GEMM1 A operand) ----------------
__global__ void k_round(const float* __restrict__ in, float* __restrict__ outp, int n4) {
    int i = blockIdx.x * blockDim.x + threadIdx.x;
    if (i >= n4) return;
    float4 v = ((const float4*)in)[i];
    v.x = __uint_as_float(to_tf32(v.x)); v.y = __uint_as_float(to_tf32(v.y));
    v.z = __uint_as_float(to_tf32(v.z)); v.w = __uint_as_float(to_tf32(v.w));
    ((float4*)outp)[i] = v;
}

// ---------------- tf32 mma.sync GEMM + fused attention logits ----------------
// Block tile 128x128, BK=16, 3-stage cp.async pipeline. 256 threads = 8 warps (4x2),
// warp tile 32x64. Inputs already tf32-rounded in gmem. Scalar-LDS fragments (R10-proven).
#define SAPITCH 20                 // 16 + 4 pad (floats)
#define STAGE_WORDS (128 * SAPITCH)
#define GEMM_DYN_SMEM (6 * STAGE_WORDS * 4)   // 3 stages x (A+B) = 61440 B

__device__ __forceinline__ void mma_tf32(float* c, const uint32_t* a, const uint32_t* b) {
    asm volatile(
        "mma.sync.aligned.m16n8k8.row.col.f32.tf32.tf32.f32 "
        "{%0,%1,%2,%3}, {%4,%5,%6,%7}, {%8,%9}, {%0,%1,%2,%3};"
        : "+f"(c[0]), "+f"(c[1]), "+f"(c[2]), "+f"(c[3])
        : "r"(a[0]), "r"(a[1]), "r"(a[2]), "r"(a[3]), "r"(b[0]), "r"(b[1]));
}

#define CP16(dst, src, sz) \
    asm volatile("cp.async.cg.shared.global [%0], [%1], 16, %2;" \
        :: "r"(dst), "l"(src), "r"(sz))
#define CP_COMMIT() asm volatile("cp.async.commit_group;" ::: "memory")
#define CP_WAIT1()  asm volatile("cp.async.wait_group 1;" ::: "memory")

__global__ __launch_bounds__(256, 2)
void k_tc_gemm(const float* __restrict__ A, const float* __restrict__ Bt,
               float* __restrict__ C,
               const float* __restrict__ asrc, const float* __restrict__ adst,
               float* __restrict__ als, float* __restrict__ ald,
               int H, int M, int Nmat, int K)
{
    extern __shared__ uint32_t dynsm[];
    uint32_t* dynA = dynsm;                    // [3][STAGE_WORDS]
    uint32_t* dynB = dynsm + 3 * STAGE_WORDS;  // [3][STAGE_WORDS]
    __shared__ float s_als[128];
    __shared__ float s_ald[128];

    int tid  = threadIdx.x;
    int lane = tid & 31;
    int warp = tid >> 5;
    int warpM = warp >> 1;          // 0..3
    int warpN = warp & 1;           // 0..1
    int g = lane >> 2;              // 0..7
    int t = lane & 3;               // 0..3

    int rowBase = blockIdx.y * 128;
    int colBase = blockIdx.x * 128;

    if (tid < 128) { s_als[tid] = 0.f; s_ald[tid] = 0.f; }

    uint32_t smA = (uint32_t)__cvta_generic_to_shared(dynA);
    uint32_t smB = (uint32_t)__cvta_generic_to_shared(dynB);

    // per-thread tile-copy coords: 2 chunks of 16B per operand per stage
    int r0 = tid >> 2,           c0 = (tid & 3) * 4;
    int r1 = (tid + 256) >> 2,   c1 = ((tid + 256) & 3) * 4;
    int ga0 = rowBase + r0, ga1 = rowBase + r1;
    const float* a0p = A + (size_t)min(ga0, M - 1) * K + c0;
    const float* a1p = A + (size_t)min(ga1, M - 1) * K + c1;
    uint32_t a0sz = (ga0 < M) ? 16 : 0;
    uint32_t a1sz = (ga1 < M) ? 16 : 0;
    const float* b0p = Bt + (size_t)(colBase + r0) * K + c0;
    const float* b1p = Bt + (size_t)(colBase + r1) * K + c1;
    uint32_t ad0 = (uint32_t)(r0 * SAPITCH + c0) << 2;
    uint32_t ad1 = (uint32_t)(r1 * SAPITCH + c1) << 2;

#define ISSUE_TILE(st, k0)                                                     \
    {                                                                          \
        uint32_t sa = smA + (st) * (STAGE_WORDS * 4);                          \
        uint32_t sb = smB + (st) * (STAGE_WORDS * 4);                          \
        CP16(sa + ad0, a0p + (k0), a0sz);                                      \
        CP16(sa + ad1, a1p + (k0), a1sz);                                      \
        CP16(sb + ad0, b0p + (k0), 16u);                                       \
        CP16(sb + ad1, b1p + (k0), 16u);                                       \
    }

    float acc[2][8][4];
#pragma unroll
    for (int i = 0; i < 2; i++)
#pragma unroll
        for (int j = 0; j < 8; j++)
#pragma unroll
            for (int q = 0; q < 4; q++) acc[i][j][q] = 0.f;

    int iters = K >> 4;     // >= 16 for all layers
    ISSUE_TILE(0, 0);  CP_COMMIT();
    ISSUE_TILE(1, 16); CP_COMMIT();

    for (int it = 0; it < iters; it++) {
        CP_WAIT1();
        __syncthreads();
        int cur = it - (it / 3) * 3;
        const uint32_t* sA = dynA + cur * STAGE_WORDS;
        const uint32_t* sB = dynB + cur * STAGE_WORDS;

#pragma unroll
        for (int ks = 0; ks < 16; ks += 8) {
            uint32_t a[2][4], b[8][2];
#pragma unroll
            for (int mt = 0; mt < 2; mt++) {
                int row = warpM * 32 + mt * 16 + g;
                a[mt][0] = sA[row * SAPITCH + ks + t];
                a[mt][1] = sA[(row + 8) * SAPITCH + ks + t];
                a[mt][2] = sA[row * SAPITCH + ks + t + 4];
                a[mt][3] = sA[(row + 8) * SAPITCH + ks + t + 4];
            }
#pragma unroll
            for (int nt = 0; nt < 8; nt++) {
                int col = warpN * 64 + nt * 8 + g;
                b[nt][0] = sB[col * SAPITCH + ks + t];
                b[nt][1] = sB[col * SAPITCH + ks + t + 4];
            }
#pragma unroll
            for (int mt = 0; mt < 2; mt++)
#pragma unroll
                for (int nt = 0; nt < 8; nt++)
                    mma_tf32(acc[mt][nt], a[mt], b[nt]);
        }

        if (it + 2 < iters) {
            int nst = it + 2;
            nst -= (nst / 3) * 3;
            ISSUE_TILE(nst, (it + 2) << 4);
        }
        CP_COMMIT();
    }

    // ---- C store ----
#pragma unroll
    for (int mt = 0; mt < 2; mt++) {
        int row = rowBase + warpM * 32 + mt * 16 + g;
#pragma unroll
        for (int nt = 0; nt < 8; nt++) {
            int col = colBase + warpN * 64 + nt * 8 + 2 * t;
            if (row < M)
                *(float2*)(C + (size_t)row * Nmat + col) =
                    make_float2(acc[mt][nt][0], acc[mt][nt][1]);
            if (row + 8 < M)
                *(float2*)(C + (size_t)(row + 8) * Nmat + col) =
                    make_float2(acc[mt][nt][2], acc[mt][nt][3]);
        }
    }

    // ---- fused attn logits: als/ald for this (row block, head) ----
    {
        int hd = blockIdx.x;                        // colBase / 128
        const float* as = asrc + hd * HID;
        const float* ad = adst + hd * HID;
#pragma unroll
        for (int mt = 0; mt < 2; mt++) {
            float ps0 = 0.f, pd0 = 0.f, ps1 = 0.f, pd1 = 0.f;
#pragma unroll
            for (int nt = 0; nt < 8; nt++) {
                int cih = warpN * 64 + nt * 8 + 2 * t;
                float a0 = as[cih], a1 = as[cih + 1];
                float d0 = ad[cih], d1 = ad[cih + 1];
                ps0 += acc[mt][nt][0] * a0 + acc[mt][nt][1] * a1;
                pd0 += acc[mt][nt][0] * d0 + acc[mt][nt][1] * d1;
                ps1 += acc[mt][nt][2] * a0 + acc[mt][nt][3] * a1;
                pd1 += acc[mt][nt][2] * d0 + acc[mt][nt][3] * d1;
            }
            int rl = warpM * 32 + mt * 16 + g;
            atomicAdd(&s_als[rl], ps0);     atomicAdd(&s_ald[rl], pd0);
            atomicAdd(&s_als[rl + 8], ps1); atomicAdd(&s_ald[rl + 8], pd1);
        }
        __syncthreads();
        if (tid < 128) {
            int row = rowBase + tid;
            if (row < M) {
                als[row * H + hd] = s_als[tid];
                ald[row * H + hd] = s_ald[tid];
            }
        }
    }
#undef ISSUE_TILE
}

// ---------------- fused edge-softmax + aggregate: block=node, warp=head ----------------
__device__ __forceinline__ float leaky02(float x) { return x > 0.f ? x : 0.2f * x; }
__device__ __forceinline__ float eluf(float x)    { return x > 0.f ? x : expm1f(x); }

__device__ __forceinline__ float4 agg_head(const float* __restrict__ h,
                                           const float* __restrict__ als,
                                           float ald, int hd, int H, int D,
                                           int start, int end, int lane)
{
    // pass 1: warp-level max & expsum
    float m = -1e30f;
    for (int i = start + lane; i < end; i += 32)
        m = fmaxf(m, leaky02(als[g_csr[i] * H + hd] + ald));
#pragma unroll
    for (int o = 16; o > 0; o >>= 1) m = fmaxf(m, __shfl_xor_sync(0xffffffffu, m, o));
    float ssum = 0.f;
    for (int i = start + lane; i < end; i += 32)
        ssum += __expf(leaky02(als[g_csr[i] * H + hd] + ald) - m);
#pragma unroll
    for (int o = 16; o > 0; o >>= 1) ssum += __shfl_xor_sync(0xffffffffu, ssum, o);
    float inv = 1.f / (ssum + 1e-16f);

    // pass 2: weighted float4 gather; weights/srcs broadcast via shfl
    float4 acc = make_float4(0.f, 0.f, 0.f, 0.f);
    const float4* h4 = (const float4*)h;
    int rowStride = D >> 2;
    int colOff = hd * 32 + lane;
    for (int base = start; base < end; base += 32) {
        int e = base + lane;
        int s = 0; float w = 0.f;
        if (e < end) {
            s = g_csr[e];
            w = __expf(leaky02(als[s * H + hd] + ald) - m) * inv;
        }
        int cnt = min(32, end - base);
#pragma unroll 4
        for (int j = 0; j < cnt; j++) {
            int   sj = __shfl_sync(0xffffffffu, s, j);
            float wj = __shfl_sync(0xffffffffu, w, j);
            float4 v = h4[(size_t)sj * rowStride + colOff];
            acc.x += wj * v.x; acc.y += wj * v.y;
            acc.z += wj * v.z; acc.w += wj * v.w;
        }
    }
    return acc;
}

// MODE 1: out = tf32(elu(acc + bias)); MODE 2: out = tf32(elu(resid + acc + bias))
// Outputs are tf32-rounded so the next GEMM can cp.async them directly.
template <int MODE>
__global__ void k_agg(const float* __restrict__ h, const float* __restrict__ als,
                      const float* __restrict__ aldp, const float* __restrict__ bias,
                      const float* __restrict__ resid, float* __restrict__ out,
                      int H, int D)
{
    int node = blockIdx.x;
    int hd   = threadIdx.y;
    int lane = threadIdx.x;
    int start = g_offs[node], end = g_offs[node + 1];
    float ald = aldp[node * H + hd];

    float4 acc = agg_head(h, als, ald, hd, H, D, start, end, lane);

    int col = hd * HID + lane * 4;
    const float4 b = *(const float4*)(bias + col);
    float4 o_;
    if (MODE == 1) {
        o_.x = eluf(acc.x + b.x); o_.y = eluf(acc.y + b.y);
        o_.z = eluf(acc.z + b.z); o_.w = eluf(acc.w + b.w);
    } else {
        const float4 r = *(const float4*)(resid + (size_t)node * D + col);
        o_.x = eluf(acc.x + b.x + r.x); o_.y = eluf(acc.y + b.y + r.y);
        o_.z = eluf(acc.z + b.z + r.z); o_.w = eluf(acc.w + b.w + r.w);
    }
    o_.x = __uint_as_float(to_tf32(o_.x)); o_.y = __uint_as_float(to_tf32(o_.y));
    o_.z = __uint_as_float(to_tf32(o_.z)); o_.w = __uint_as_float(to_tf32(o_.w));
    *(float4*)(out + (size_t)node * D + col) = o_;
}

// Layer-3 agg fused with head-mean + bias + global mean pool (atomic into g_pooled)
__global__ void k_agg3(const float* __restrict__ h, const float* __restrict__ als,
                       const float* __restrict__ aldp, const float* __restrict__ b3,
                       const int* __restrict__ batch)
{
    __shared__ float4 sacc[H3N][32];

    int node = blockIdx.x;
    int hd   = threadIdx.y;
    int lane = threadIdx.x;
    int start = g_offs[node], end = g_offs[node + 1];
    float ald = aldp[node * H3N + hd];

    float4 acc = agg_head(h, als, ald, hd, H3N, D3, start, end, lane);
    sacc[hd][lane] = acc;
    __syncthreads();

    if (hd == 0) {
        float4 a0 = sacc[0][lane], a1 = sacc[1][lane], a2 = sacc[2][lane];
        const float4 b = *(const float4*)(b3 + lane * 4);
        float4 v;
        v.x = (a0.x + a1.x + a2.x) * (1.f / 3.f) + b.x;
        v.y = (a0.y + a1.y + a2.y) * (1.f / 3.f) + b.y;
        v.z = (a0.z + a1.z + a2.z) * (1.f / 3.f) + b.z;
        v.w = (a0.w + a1.w + a2.w) * (1.f / 3.f) + b.w;
        int grp = batch[node];
        float* pp = g_pooled + grp * HID + lane * 4;
        atomicAdd(pp + 0, v.x);
        atomicAdd(pp + 1, v.y);
        atomicAdd(pp + 2, v.z);
        atomicAdd(pp + 3, v.w);
        if (lane == 0) atomicAdd(&g_cnt[grp], 1);
    }
}

__global__ void k_classify(const float* __restrict__ Wc, const float* __restrict__ bc,
                           float* __restrict__ out, int out_size)
{
    __shared__ float lg[GG * NCLS];
    __shared__ float rowm[GG], rowl[GG];
    int t = threadIdx.x;            // 640 threads
    int g = t / NCLS, c = t - g * NCLS;
    float cnt = (float)max(g_cnt[g], 1);
    float s = 0.f;
#pragma unroll
    for (int k = 0; k < HID; k++) s += g_pooled[g * HID + k] * Wc[k * NCLS + c];
    float logit = s / cnt + bc[c];
    lg[t] = logit;
    __syncthreads();
    if (t < GG) {
        float m = -1e30f;
        for (int j = 0; j < NCLS; j++) m = fmaxf(m, lg[t * NCLS + j]);
        float se = 0.f;
        for (int j = 0; j < NCLS; j++) se += expf(lg[t * NCLS + j] - m);
        rowm[t] = m; rowl[t] = logf(se);
    }
    __syncthreads();
    out[t] = logit;
    if (out_size >= 2 * GG * NCLS)
        out[GG * NCLS + t] = logit - rowm[g] - rowl[g];
}

// ---------------- launch ----------------
extern "C" void kernel_launch(void* const* d_in, const int* in_sizes, int n_in,
                              void* d_out, int out_size)
{
    const float* x     = (const float*)d_in[0];
    const int*   ei    = (const int*)  d_in[1];
    const int*   batch = (const int*)  d_in[2];
    const float* W1  = (const float*)d_in[3];
    const float* a1s = (const float*)d_in[4];
    const float* a1d = (const float*)d_in[5];
    const float* b1  = (const float*)d_in[6];
    const float* W2  = (const float*)d_in[7];
    const float* a2s = (const float*)d_in[8];
    const float* a2d = (const float*)d_in[9];
    const float* b2  = (const float*)d_in[10];
    const float* W3  = (const float*)d_in[11];
    const float* a3s = (const float*)d_in[12];
    const float* a3d = (const float*)d_in[13];
    const float* b3  = (const float*)d_in[14];
    const float* Wc  = (const float*)d_in[15];
    const float* bc  = (const float*)d_in[16];
    float* out = (float*)d_out;

    float *h_, *x1_, *x2_, *als_, *ald_, *wt1_, *wt2_, *wt3_;
    cudaGetSymbolAddress((void**)&h_,  g_h);
    cudaGetSymbolAddress((void**)&x1_, g_x1);
    cudaGetSymbolAddress((void**)&x2_, g_x2);
    cudaGetSymbolAddress((void**)&als_, g_als);
    cudaGetSymbolAddress((void**)&ald_, g_ald);
    cudaGetSymbolAddress((void**)&wt1_, g_Wt1);
    cudaGetSymbolAddress((void**)&wt2_, g_Wt2);
    cudaGetSymbolAddress((void**)&wt3_, g_Wt3);

    cudaFuncSetAttribute(k_tc_gemm, cudaFuncAttributeMaxDynamicSharedMemorySize,
                         GEMM_DYN_SMEM);

    dim3 tb(32, 8);

    // Slots 0-2 (keep gemm1 at profiled slot 3): transposes for W1/W2 + round x.
    k_transpose<<<dim3(D1 / 32, FIN / 32), tb>>>(W1, wt1_, FIN, D1);      // 0
    k_transpose<<<dim3(D1 / 32, D1 / 32), tb>>>(W2, wt2_, D1, D1);        // 1
    k_round<<<(NN * FIN / 4 + 255) / 256, 256>>>(x, x2_, NN * FIN / 4);   // 2 (x2_ as scratch)

    // Layer-1 GEMM (+fused attn)                                         // 3
    k_tc_gemm<<<dim3(D1 / 128, (NN + 127) / 128), 256, GEMM_DYN_SMEM>>>(
        x2_, wt1_, h_, a1s, a1d, als_, ald_, H1N, NN, D1, FIN);

    // CSR by dst + W3 transpose (independent of layer1 results)
    k_zero   <<<(NN + 255) / 256, 256>>>();
    k_count  <<<(ET + 255) / 256, 256>>>(ei);
    k_scan   <<<1, 1024>>>();
    k_scatter<<<(ET + 255) / 256, 256>>>(ei);
    k_transpose<<<dim3(D3 / 32, D1 / 32), tb>>>(W3, wt3_, D1, D3);

    // Layer 1 aggregate (emits tf32-rounded x1)
    k_agg<1><<<NN, dim3(32, H1N)>>>(h_, als_, ald_, b1, nullptr, x1_, H1N, D1);

    // Layer 2 (residual; emits tf32-rounded x2 — scratch reuse is done by now)
    k_tc_gemm<<<dim3(D1 / 128, (NN + 127) / 128), 256, GEMM_DYN_SMEM>>>(
        x1_, wt2_, h_, a2s, a2d, als_, ald_, H1N, NN, D1, D1);
    k_agg<2><<<NN, dim3(32, H1N)>>>(h_, als_, ald_, b2, x1_, x2_, H1N, D1);

    // Layer 3 (head mean + pool fused)
    k_tc_gemm<<<dim3(D3 / 128, (NN + 127) / 128), 256, GEMM_DYN_SMEM>>>(
        x2_, wt3_, h_, a3s, a3d, als_, ald_, H3N, NN, D3, D1);
    k_agg3<<<NN, dim3(32, H3N)>>>(h_, als_, ald_, b3, batch);

    // Classify
    k_classify<<<1, GG * NCLS>>>(Wc, bc, out, out_size);
}

// round 15
// speedup vs baseline: 1.5643x; 1.0052x over previous
#include <cuda_runtime.h>
#include <cuda_bf16.h>
#include <math.h>
#include <stdint.h>

// ---------------- problem constants ----------------
#define NN   10000
#define EE   160000
#define ET   (EE + NN)      // edges + self loops
#define FIN  256
#define HID  128
#define H1N  5
#define H3N  3
#define D1   (H1N * HID)    // 640
#define D3   (H3N * HID)    // 384
#define GG   64
#define NCLS 10

// ---------------- device scratch (static globals: no allocation) ----------------
__device__ __nv_bfloat16 g_hb[NN * D1];   // projected features, bf16 (agg gather)
__device__ float g_x1[NN * D1];
__device__ float g_x2[NN * D1];           // also reused as rounded-x scratch for GEMM1
__device__ float g_als[NN * H1N];
__device__ float g_ald[NN * H1N];
__device__ float g_Wt1[FIN * D1];
__device__ float g_Wt2[D1 * D1];
__device__ float g_Wt3[D1 * D3];
__device__ int   g_deg[NN];
__device__ int   g_offs[NN + 1];
__device__ int   g_cur[NN];
__device__ int   g_csr[ET];
__device__ float g_pooled[GG * HID];
__device__ int   g_cnt[GG];

__device__ __forceinline__ uint32_t to_tf32(float x) {
    uint32_t u;
    asm("cvt.rna.tf32.f32 %0, %1;" : "=r"(u) : "f"(x));
    return u;
}

// ---------------- CSR build ----------------
__global__ void k_zero() {
    int i = blockIdx.x * blockDim.x + threadIdx.x;
    if (i < NN) g_deg[i] = 0;
    if (i < GG * HID) g_pooled[i] = 0.f;
    if (i < GG) g_cnt[i] = 0;
}

__global__ void k_count(const int* __restrict__ ei) {
    int e = blockIdx.x * blockDim.x + threadIdx.x;
    if (e >= ET) return;
    int dst = (e < EE) ? ei[EE + e] : (e - EE);
    atomicAdd(&g_deg[dst], 1);
}

__global__ void k_scan() {
    __shared__ int sh[1024];
    __shared__ int carry;
    int tid = threadIdx.x;
    if (tid == 0) carry = 0;
    __syncthreads();
    for (int base = 0; base < NN; base += 1024) {
        int i = base + tid;
        int v = (i < NN) ? g_deg[i] : 0;
        sh[tid] = v;
        __syncthreads();
        for (int off = 1; off < 1024; off <<= 1) {
            int t = (tid >= off) ? sh[tid - off] : 0;
            __syncthreads();
            sh[tid] += t;
            __syncthreads();
        }
        int excl = sh[tid] - v + carry;
        if (i < NN) { g_offs[i] = excl; g_cur[i] = excl; }
        __syncthreads();
        if (tid == 1023) carry += sh[1023];
        __syncthreads();
    }
    if (tid == 0) g_offs[NN] = carry;
}

__global__ void k_scatter(const int* __restrict__ ei) {
    int e = blockIdx.x * blockDim.x + threadIdx.x;
    if (e >= ET) return;
    int src, dst;
    if (e < EE) { src = ei[e]; dst = ei[EE + e]; }
    else        { src = dst = e - EE; }
    int pos = atomicAdd(&g_cur[dst], 1);
    g_csr[pos] = src;
}

// ---------------- weight transpose (+tf32 rounding): Wt[n][k] = tf32(W[k][n]) ----------------
__global__ void k_transpose(const float* __restrict__ W, float* __restrict__ Wt,
                            int K, int N) {
    __shared__ float t[32][33];
    int nb = blockIdx.x * 32, kb = blockIdx.y * 32;
    int x = threadIdx.x, y = threadIdx.y;
#pragma unroll
    for (int i = 0; i < 32; i += 8) {
        int k = kb + y + i, n = nb + x;
        t[y + i][x] = (k < K && n < N) ? W[(size_t)k * N + n] : 0.f;
    }
    __syncthreads();
#pragma unroll
    for (int i = 0; i < 32; i += 8) {
        int n = nb + y + i, k = kb + x;
        if (n < N && k < K)
            Wt[(size_t)n * K + k] = __uint_as_float(to_tf32(t[x][y + i]));
    }
}

// ---------------- tf32 rounding pass (for GEMM1 A operand) ----------------
__global__ void k_round(const float* __restrict__ in, float* __restrict__ outp, int n4) {
    int i = blockIdx.x * blockDim.x + threadIdx.x;
    if (i >= n4) return;
    float4 v = ((const float4*)in)[i];
    v.x = __uint_as_float(to_tf32(v.x)); v.y = __uint_as_float(to_tf32(v.y));
    v.z = __uint_as_float(to_tf32(v.z)); v.w = __uint_as_float(to_tf32(v.w));
    ((float4*)outp)[i] = v;
}

// ---------------- tf32 mma.sync GEMM + fused attention logits, bf16 C ----------------
// Block tile 128x128, BK=16, 3-stage cp.async pipeline. 256 threads = 8 warps (4x2),
// warp tile 32x64. Inputs already tf32-rounded in gmem. Scalar-LDS fragments.
#define SAPITCH 20                 // 16 + 4 pad (floats)
#define STAGE_WORDS (128 * SAPITCH)
#define GEMM_DYN_SMEM (6 * STAGE_WORDS * 4)   // 3 stages x (A+B) = 61440 B

__device__ __forceinline__ void mma_tf32(float* c, const uint32_t* a, const uint32_t* b) {
    asm volatile(
        "mma.sync.aligned.m16n8k8.row.col.f32.tf32.tf32.f32 "
        "{%0,%1,%2,%3}, {%4,%5,%6,%7}, {%8,%9}, {%0,%1,%2,%3};"
        : "+f"(c[0]), "+f"(c[1]), "+f"(c[2]), "+f"(c[3])
        : "r"(a[0]), "r"(a[1]), "r"(a[2]), "r"(a[3]), "r"(b[0]), "r"(b[1]));
}

#define CP16(dst, src, sz) \
    asm volatile("cp.async.cg.shared.global [%0], [%1], 16, %2;" \
        :: "r"(dst), "l"(src), "r"(sz))
#define CP_COMMIT() asm volatile("cp.async.commit_group;" ::: "memory")
#define CP_WAIT1()  asm volatile("cp.async.wait_group 1;" ::: "memory")

__global__ __launch_bounds__(256, 2)
void k_tc_gemm(const float* __restrict__ A, const float* __restrict__ Bt,
               __nv_bfloat16* __restrict__ C,
               const float* __restrict__ asrc, const float* __restrict__ adst,
               float* __restrict__ als, float* __restrict__ ald,
               int H, int M, int Nmat, int K)
{
    extern __shared__ uint32_t dynsm[];
    uint32_t* dynA = dynsm;                    // [3][STAGE_WORDS]
    uint32_t* dynB = dynsm + 3 * STAGE_WORDS;  // [3][STAGE_WORDS]
    __shared__ float s_als[128];
    __shared__ float s_ald[128];

    int tid  = threadIdx.x;
    int lane = tid & 31;
    int warp = tid >> 5;
    int warpM = warp >> 1;          // 0..3
    int warpN = warp & 1;           // 0..1
    int g = lane >> 2;              // 0..7
    int t = lane & 3;               // 0..3

    int rowBase = blockIdx.y * 128;
    int colBase = blockIdx.x * 128;

    if (tid < 128) { s_als[tid] = 0.f; s_ald[tid] = 0.f; }

    uint32_t smA = (uint32_t)__cvta_generic_to_shared(dynA);
    uint32_t smB = (uint32_t)__cvta_generic_to_shared(dynB);

    // per-thread tile-copy coords: 2 chunks of 16B per operand per stage
    int r0 = tid >> 2,           c0 = (tid & 3) * 4;
    int r1 = (tid + 256) >> 2,   c1 = ((tid + 256) & 3) * 4;
    int ga0 = rowBase + r0, ga1 = rowBase + r1;
    const float* a0p = A + (size_t)min(ga0, M - 1) * K + c0;
    const float* a1p = A + (size_t)min(ga1, M - 1) * K + c1;
    uint32_t a0sz = (ga0 < M) ? 16 : 0;
    uint32_t a1sz = (ga1 < M) ? 16 : 0;
    const float* b0p = Bt + (size_t)(colBase + r0) * K + c0;
    const float* b1p = Bt + (size_t)(colBase + r1) * K + c1;
    uint32_t ad0 = (uint32_t)(r0 * SAPITCH + c0) << 2;
    uint32_t ad1 = (uint32_t)(r1 * SAPITCH + c1) << 2;

#define ISSUE_TILE(st, k0)                                                     \
    {                                                                          \
        uint32_t sa = smA + (st) * (STAGE_WORDS * 4);                          \
        uint32_t sb = smB + (st) * (STAGE_WORDS * 4);                          \
        CP16(sa + ad0, a0p + (k0), a0sz);                                      \
        CP16(sa + ad1, a1p + (k0), a1sz);                                      \
        CP16(sb + ad0, b0p + (k0), 16u);                                       \
        CP16(sb + ad1, b1p + (k0), 16u);                                       \
    }

    float acc[2][8][4];
#pragma unroll
    for (int i = 0; i < 2; i++)
#pragma unroll
        for (int j = 0; j < 8; j++)
#pragma unroll
            for (int q = 0; q < 4; q++) acc[i][j][q] = 0.f;

    int iters = K >> 4;     // >= 16 for all layers
    ISSUE_TILE(0, 0);  CP_COMMIT();
    ISSUE_TILE(1, 16); CP_COMMIT();

    for (int it = 0; it < iters; it++) {
        CP_WAIT1();
        __syncthreads();
        int cur = it - (it / 3) * 3;
        const uint32_t* sA = dynA + cur * STAGE_WORDS;
        const uint32_t* sB = dynB + cur * STAGE_WORDS;

#pragma unroll
        for (int ks = 0; ks < 16; ks += 8) {
            uint32_t a[2][4], b[8][2];
#pragma unroll
            for (int mt = 0; mt < 2; mt++) {
                int row = warpM * 32 + mt * 16 + g;
                a[mt][0] = sA[row * SAPITCH + ks + t];
                a[mt][1] = sA[(row + 8) * SAPITCH + ks + t];
                a[mt][2] = sA[row * SAPITCH + ks + t + 4];
                a[mt][3] = sA[(row + 8) * SAPITCH + ks + t + 4];
            }
#pragma unroll
            for (int nt = 0; nt < 8; nt++) {
                int col = warpN * 64 + nt * 8 + g;
                b[nt][0] = sB[col * SAPITCH + ks + t];
                b[nt][1] = sB[col * SAPITCH + ks + t + 4];
            }
#pragma unroll
            for (int mt = 0; mt < 2; mt++)
#pragma unroll
                for (int nt = 0; nt < 8; nt++)
                    mma_tf32(acc[mt][nt], a[mt], b[nt]);
        }

        if (it + 2 < iters) {
            int nst = it + 2;
            nst -= (nst / 3) * 3;
            ISSUE_TILE(nst, (it + 2) << 4);
        }
        CP_COMMIT();
    }

    // ---- C store (bf16) ----
#pragma unroll
    for (int mt = 0; mt < 2; mt++) {
        int row = rowBase + warpM * 32 + mt * 16 + g;
#pragma unroll
        for (int nt = 0; nt < 8; nt++) {
            int col = colBase + warpN * 64 + nt * 8 + 2 * t;
            if (row < M)
                *(__nv_bfloat162*)(C + (size_t)row * Nmat + col) =
                    __float22bfloat162_rn(make_float2(acc[mt][nt][0], acc[mt][nt][1]));
            if (row + 8 < M)
                *(__nv_bfloat162*)(C + (size_t)(row + 8) * Nmat + col) =
                    __float22bfloat162_rn(make_float2(acc[mt][nt][2], acc[mt][nt][3]));
        }
    }

    // ---- fused attn logits (fp32 accumulators): als/ald for this (row block, head) ----
    {
        int hd = blockIdx.x;                        // colBase / 128
        const float* as = asrc + hd * HID;
        const float* ad = adst + hd * HID;
#pragma unroll
        for (int mt = 0; mt < 2; mt++) {
            float ps0 = 0.f, pd0 = 0.f, ps1 = 0.f, pd1 = 0.f;
#pragma unroll
            for (int nt = 0; nt < 8; nt++) {
                int cih = warpN * 64 + nt * 8 + 2 * t;
                float a0 = as[cih], a1 = as[cih + 1];
                float d0 = ad[cih], d1 = ad[cih + 1];
                ps0 += acc[mt][nt][0] * a0 + acc[mt][nt][1] * a1;
                pd0 += acc[mt][nt][0] * d0 + acc[mt][nt][1] * d1;
                ps1 += acc[mt][nt][2] * a0 + acc[mt][nt][3] * a1;
                pd1 += acc[mt][nt][2] * d0 + acc[mt][nt][3] * d1;
            }
            int rl = warpM * 32 + mt * 16 + g;
            atomicAdd(&s_als[rl], ps0);     atomicAdd(&s_ald[rl], pd0);
            atomicAdd(&s_als[rl + 8], ps1); atomicAdd(&s_ald[rl + 8], pd1);
        }
        __syncthreads();
        if (tid < 128) {
            int row = rowBase + tid;
            if (row < M) {
                als[row * H + hd] = s_als[tid];
                ald[row * H + hd] = s_ald[tid];
            }
        }
    }
#undef ISSUE_TILE
}

// ---------------- fused edge-softmax + aggregate: block=node, warp=head ----------------
__device__ __forceinline__ float leaky02(float x) { return x > 0.f ? x : 0.2f * x; }
__device__ __forceinline__ float eluf(float x)    { return x > 0.f ? x : expm1f(x); }

// bf16 gather: lane owns 4 channels (one uint2 = 4 bf16 per edge)
__device__ __forceinline__ float4 agg_head(const __nv_bfloat16* __restrict__ hb,
                                           const float* __restrict__ als,
                                           float ald, int hd, int H, int D,
                                           int start, int end, int lane)
{
    // pass 1: warp-level max & expsum
    float m = -1e30f;
    for (int i = start + lane; i < end; i += 32)
        m = fmaxf(m, leaky02(als[g_csr[i] * H + hd] + ald));
#pragma unroll
    for (int o = 16; o > 0; o >>= 1) m = fmaxf(m, __shfl_xor_sync(0xffffffffu, m, o));
    float ssum = 0.f;
    for (int i = start + lane; i < end; i += 32)
        ssum += __expf(leaky02(als[g_csr[i] * H + hd] + ald) - m);
#pragma unroll
    for (int o = 16; o > 0; o >>= 1) ssum += __shfl_xor_sync(0xffffffffu, ssum, o);
    float inv = 1.f / (ssum + 1e-16f);

    // pass 2: weighted bf16x4 gather; weights/srcs broadcast via shfl
    float4 acc = make_float4(0.f, 0.f, 0.f, 0.f);
    int c = hd * HID + lane * 4;
    for (int base = start; base < end; base += 32) {
        int e = base + lane;
        int s = 0; float w = 0.f;
        if (e < end) {
            s = g_csr[e];
            w = __expf(leaky02(als[s * H + hd] + ald) - m) * inv;
        }
        int cnt = min(32, end - base);
#pragma unroll 4
        for (int j = 0; j < cnt; j++) {
            int   sj = __shfl_sync(0xffffffffu, s, j);
            float wj = __shfl_sync(0xffffffffu, w, j);
            uint2 v = *(const uint2*)(hb + (size_t)sj * D + c);
            float2 f0 = __bfloat1622float2(*(__nv_bfloat162*)&v.x);
            float2 f1 = __bfloat1622float2(*(__nv_bfloat162*)&v.y);
            acc.x += wj * f0.x; acc.y += wj * f0.y;
            acc.z += wj * f1.x; acc.w += wj * f1.y;
        }
    }
    return acc;
}

// MODE 1: out = tf32(elu(acc + bias)); MODE 2: out = tf32(elu(resid + acc + bias))
// Outputs tf32-rounded so the next GEMM can cp.async them directly.
template <int MODE>
__global__ void k_agg(const __nv_bfloat16* __restrict__ hb, const float* __restrict__ als,
                      const float* __restrict__ aldp, const float* __restrict__ bias,
                      const float* __restrict__ resid, float* __restrict__ out,
                      int H, int D)
{
    int node = blockIdx.x;
    int hd   = threadIdx.y;
    int lane = threadIdx.x;
    int start = g_offs[node], end = g_offs[node + 1];
    float ald = aldp[node * H + hd];

    float4 acc = agg_head(hb, als, ald, hd, H, D, start, end, lane);

    int col = hd * HID + lane * 4;
    const float4 b = *(const float4*)(bias + col);
    float4 o_;
    if (MODE == 1) {
        o_.x = eluf(acc.x + b.x); o_.y = eluf(acc.y + b.y);
        o_.z = eluf(acc.z + b.z); o_.w = eluf(acc.w + b.w);
    } else {
        const float4 r = *(const float4*)(resid + (size_t)node * D + col);
        o_.x = eluf(acc.x + b.x + r.x); o_.y = eluf(acc.y + b.y + r.y);
        o_.z = eluf(acc.z + b.z + r.z); o_.w = eluf(acc.w + b.w + r.w);
    }
    o_.x = __uint_as_float(to_tf32(o_.x)); o_.y = __uint_as_float(to_tf32(o_.y));
    o_.z = __uint_as_float(to_tf32(o_.z)); o_.w = __uint_as_float(to_tf32(o_.w));
    *(float4*)(out + (size_t)node * D + col) = o_;
}

// Layer-3 agg fused with head-mean + bias + global mean pool (atomic into g_pooled)
__global__ void k_agg3(const __nv_bfloat16* __restrict__ hb, const float* __restrict__ als,
                       const float* __restrict__ aldp, const float* __restrict__ b3,
                       const int* __restrict__ batch)
{
    __shared__ float4 sacc[H3N][32];

    int node = blockIdx.x;
    int hd   = threadIdx.y;
    int lane = threadIdx.x;
    int start = g_offs[node], end = g_offs[node + 1];
    float ald = aldp[node * H3N + hd];

    float4 acc = agg_head(hb, als, ald, hd, H3N, D3, start, end, lane);
    sacc[hd][lane] = acc;
    __syncthreads();

    if (hd == 0) {
        float4 a0 = sacc[0][lane], a1 = sacc[1][lane], a2 = sacc[2][lane];
        const float4 b = *(const float4*)(b3 + lane * 4);
        float4 v;
        v.x = (a0.x + a1.x + a2.x) * (1.f / 3.f) + b.x;
        v.y = (a0.y + a1.y + a2.y) * (1.f / 3.f) + b.y;
        v.z = (a0.z + a1.z + a2.z) * (1.f / 3.f) + b.z;
        v.w = (a0.w + a1.w + a2.w) * (1.f / 3.f) + b.w;
        int grp = batch[node];
        float* pp = g_pooled + grp * HID + lane * 4;
        atomicAdd(pp + 0, v.x);
        atomicAdd(pp + 1, v.y);
        atomicAdd(pp + 2, v.z);
        atomicAdd(pp + 3, v.w);
        if (lane == 0) atomicAdd(&g_cnt[grp], 1);
    }
}

__global__ void k_classify(const float* __restrict__ Wc, const float* __restrict__ bc,
                           float* __restrict__ out, int out_size)
{
    __shared__ float lg[GG * NCLS];
    __shared__ float rowm[GG], rowl[GG];
    int t = threadIdx.x;            // 640 threads
    int g = t / NCLS, c = t - g * NCLS;
    float cnt = (float)max(g_cnt[g], 1);
    float s = 0.f;
#pragma unroll
    for (int k = 0; k < HID; k++) s += g_pooled[g * HID + k] * Wc[k * NCLS + c];
    float logit = s / cnt + bc[c];
    lg[t] = logit;
    __syncthreads();
    if (t < GG) {
        float m = -1e30f;
        for (int j = 0; j < NCLS; j++) m = fmaxf(m, lg[t * NCLS + j]);
        float se = 0.f;
        for (int j = 0; j < NCLS; j++) se += expf(lg[t * NCLS + j] - m);
        rowm[t] = m; rowl[t] = logf(se);
    }
    __syncthreads();
    out[t] = logit;
    if (out_size >= 2 * GG * NCLS)
        out[GG * NCLS + t] = logit - rowm[g] - rowl[g];
}

// ---------------- launch ----------------
extern "C" void kernel_launch(void* const* d_in, const int* in_sizes, int n_in,
                              void* d_out, int out_size)
{
    const float* x     = (const float*)d_in[0];
    const int*   ei    = (const int*)  d_in[1];
    const int*   batch = (const int*)  d_in[2];
    const float* W1  = (const float*)d_in[3];
    const float* a1s = (const float*)d_in[4];
    const float* a1d = (const float*)d_in[5];
    const float* b1  = (const float*)d_in[6];
    const float* W2  = (const float*)d_in[7];
    const float* a2s = (const float*)d_in[8];
    const float* a2d = (const float*)d_in[9];
    const float* b2  = (const float*)d_in[10];
    const float* W3  = (const float*)d_in[11];
    const float* a3s = (const float*)d_in[12];
    const float* a3d = (const float*)d_in[13];
    const float* b3  = (const float*)d_in[14];
    const float* Wc  = (const float*)d_in[15];
    const float* bc  = (const float*)d_in[16];
    float* out = (float*)d_out;

    float *x1_, *x2_, *als_, *ald_, *wt1_, *wt2_, *wt3_;
    __nv_bfloat16* hb_;
    cudaGetSymbolAddress((void**)&hb_, g_hb);
    cudaGetSymbolAddress((void**)&x1_, g_x1);
    cudaGetSymbolAddress((void**)&x2_, g_x2);
    cudaGetSymbolAddress((void**)&als_, g_als);
    cudaGetSymbolAddress((void**)&ald_, g_ald);
    cudaGetSymbolAddress((void**)&wt1_, g_Wt1);
    cudaGetSymbolAddress((void**)&wt2_, g_Wt2);
    cudaGetSymbolAddress((void**)&wt3_, g_Wt3);

    cudaFuncSetAttribute(k_tc_gemm, cudaFuncAttributeMaxDynamicSharedMemorySize,
                         GEMM_DYN_SMEM);

    dim3 tb(32, 8);

    // Slots 0-2 (keep gemm1 at profiled slot 3): transposes for W1/W2 + round x.
    k_transpose<<<dim3(D1 / 32, FIN / 32), tb>>>(W1, wt1_, FIN, D1);      // 0
    k_transpose<<<dim3(D1 / 32, D1 / 32), tb>>>(W2, wt2_, D1, D1);        // 1
    k_round<<<(NN * FIN / 4 + 255) / 256, 256>>>(x, x2_, NN * FIN / 4);   // 2 (x2_ as scratch)

    // Layer-1 GEMM (+fused attn)                                         // 3
    k_tc_gemm<<<dim3(D1 / 128, (NN + 127) / 128), 256, GEMM_DYN_SMEM>>>(
        x2_, wt1_, hb_, a1s, a1d, als_, ald_, H1N, NN, D1, FIN);

    // CSR by dst + W3 transpose (independent of layer1 results)
    k_zero   <<<(NN + 255) / 256, 256>>>();
    k_count  <<<(ET + 255) / 256, 256>>>(ei);
    k_scan   <<<1, 1024>>>();
    k_scatter<<<(ET + 255) / 256, 256>>>(ei);
    k_transpose<<<dim3(D3 / 32, D1 / 32), tb>>>(W3, wt3_, D1, D3);

    // Layer 1 aggregate (emits tf32-rounded x1)
    k_agg<1><<<NN, dim3(32, H1N)>>>(hb_, als_, ald_, b1, nullptr, x1_, H1N, D1);

    // Layer 2 (residual; emits tf32-rounded x2 — scratch reuse is done by now)
    k_tc_gemm<<<dim3(D1 / 128, (NN + 127) / 128), 256, GEMM_DYN_SMEM>>>(
        x1_, wt2_, hb_, a2s, a2d, als_, ald_, H1N, NN, D1, D1);
    k_agg<2><<<NN, dim3(32, H1N)>>>(hb_, als_, ald_, b2, x1_, x2_, H1N, D1);

    // Layer 3 (head mean + pool fused)
    k_tc_gemm<<<dim3(D3 / 128, (NN + 127) / 128), 256, GEMM_DYN_SMEM>>>(
        x2_, wt3_, hb_, a3s, a3d, als_, ald_, H3N, NN, D3, D1);
    k_agg3<<<NN, dim3(32, H3N)>>>(hb_, als_, ald_, b3, batch);

    // Classify
    k_classify<<<1, GG * NCLS>>>(Wc, bc, out, out_size);
}

// round 16
// speedup vs baseline: 1.6098x; 1.0291x over previous
#include <cuda_runtime.h>
#include <math.h>
#include <stdint.h>

// ---------------- problem constants ----------------
#define NN   10000
#define EE   160000
#define ET   (EE + NN)      // edges + self loops
#define FIN  256
#define HID  128
#define H1N  5
#define H3N  3
#define D1   (H1N * HID)    // 640
#define D3   (H3N * HID)    // 384
#define GG   64
#define NCLS 10

// ---------------- device scratch (static globals: no allocation) ----------------
__device__ float g_h [NN * D1];
__device__ float g_x1[NN * D1];
__device__ float g_x2[NN * D1];      // also reused as rounded-x scratch for GEMM1
__device__ float g_als[NN * H1N];
__device__ float g_ald[NN * H1N];
__device__ float g_Wt1[FIN * D1];
__device__ float g_Wt2[D1 * D1];
__device__ float g_Wt3[D1 * D3];
__device__ int   g_deg[NN];
__device__ int   g_offs[NN + 1];
__device__ int   g_cur[NN];
__device__ int   g_csr[ET];
__device__ float g_pooled[GG * HID];
__device__ int   g_cnt[GG];

__device__ __forceinline__ uint32_t to_tf32(float x) {
    uint32_t u;
    asm("cvt.rna.tf32.f32 %0, %1;" : "=r"(u) : "f"(x));
    return u;
}

// ---------------- CSR build ----------------
__global__ void k_zero() {
    int i = blockIdx.x * blockDim.x + threadIdx.x;
    if (i < NN) g_deg[i] = 0;
    if (i < GG * HID) g_pooled[i] = 0.f;
    if (i < GG) g_cnt[i] = 0;
}

__global__ void k_count(const int* __restrict__ ei) {
    int e = blockIdx.x * blockDim.x + threadIdx.x;
    if (e >= ET) return;
    int dst = (e < EE) ? ei[EE + e] : (e - EE);
    atomicAdd(&g_deg[dst], 1);
}

// warp-shuffle hierarchical scan: 1024 threads, 3 barriers per 1024-chunk
__global__ void k_scan() {
    __shared__ int wsum[32];
    __shared__ int carry;
    int tid  = threadIdx.x;
    int lane = tid & 31;
    int wid  = tid >> 5;
    if (tid == 0) carry = 0;
    __syncthreads();
    for (int base = 0; base < NN; base += 1024) {
        int i = base + tid;
        int v = (i < NN) ? g_deg[i] : 0;
        // warp inclusive scan
        int x = v;
#pragma unroll
        for (int o = 1; o < 32; o <<= 1) {
            int y = __shfl_up_sync(0xffffffffu, x, o);
            if (lane >= o) x += y;
        }
        if (lane == 31) wsum[wid] = x;
        __syncthreads();
        if (wid == 0) {
            int s = wsum[lane];
#pragma unroll
            for (int o = 1; o < 32; o <<= 1) {
                int y = __shfl_up_sync(0xffffffffu, s, o);
                if (lane >= o) s += y;
            }
            wsum[lane] = s;    // inclusive warp-total scan
        }
        __syncthreads();
        int excl = x - v + (wid ? wsum[wid - 1] : 0) + carry;
        if (i < NN) { g_offs[i] = excl; g_cur[i] = excl; }
        __syncthreads();
        if (tid == 0) carry += wsum[31];
        __syncthreads();
    }
    if (tid == 0) g_offs[NN] = carry;
}

__global__ void k_scatter(const int* __restrict__ ei) {
    int e = blockIdx.x * blockDim.x + threadIdx.x;
    if (e >= ET) return;
    int src, dst;
    if (e < EE) { src = ei[e]; dst = ei[EE + e]; }
    else        { src = dst = e - EE; }
    int pos = atomicAdd(&g_cur[dst], 1);
    g_csr[pos] = src;
}

// ---------------- merged weight transposes (+tf32 rounding) ----------------
// z=0: W1[FIN,D1]->Wt1 ; z=1: W2[D1,D1]->Wt2 ; z=2: W3[D1,D3]->Wt3
__global__ void k_transpose_all(const float* __restrict__ W1, const float* __restrict__ W2,
                                const float* __restrict__ W3) {
    __shared__ float t[32][33];
    const float* W; float* Wt; int K, N;
    if (blockIdx.z == 0)      { W = W1; Wt = g_Wt1; K = FIN; N = D1; }
    else if (blockIdx.z == 1) { W = W2; Wt = g_Wt2; K = D1;  N = D1; }
    else                      { W = W3; Wt = g_Wt3; K = D1;  N = D3; }
    int nb = blockIdx.x * 32, kb = blockIdx.y * 32;
    if (nb >= N || kb >= K) return;
    int x = threadIdx.x, y = threadIdx.y;
#pragma unroll
    for (int i = 0; i < 32; i += 8) {
        int k = kb + y + i, n = nb + x;
        t[y + i][x] = (k < K && n < N) ? W[(size_t)k * N + n] : 0.f;
    }
    __syncthreads();
#pragma unroll
    for (int i = 0; i < 32; i += 8) {
        int n = nb + y + i, k = kb + x;
        if (n < N && k < K)
            Wt[(size_t)n * K + k] = __uint_as_float(to_tf32(t[x][y + i]));
    }
}

// ---------------- tf32 rounding pass (for GEMM1 A operand) ----------------
__global__ void k_round(const float* __restrict__ in, float* __restrict__ outp, int n4) {
    int i = blockIdx.x * blockDim.x + threadIdx.x;
    if (i >= n4) return;
    float4 v = ((const float4*)in)[i];
    v.x = __uint_as_float(to_tf32(v.x)); v.y = __uint_as_float(to_tf32(v.y));
    v.z = __uint_as_float(to_tf32(v.z)); v.w = __uint_as_float(to_tf32(v.w));
    ((float4*)outp)[i] = v;
}

// ---------------- tf32 mma.sync GEMM + fused attention logits ----------------
// Block tile 128x128, BK=16, 3-stage cp.async pipeline. 256 threads = 8 warps (4x2),
// warp tile 32x64. Inputs already tf32-rounded in gmem. Scalar-LDS fragments.
#define SAPITCH 20                 // 16 + 4 pad (floats)
#define STAGE_WORDS (128 * SAPITCH)
#define GEMM_DYN_SMEM (6 * STAGE_WORDS * 4)   // 3 stages x (A+B) = 61440 B

__device__ __forceinline__ void mma_tf32(float* c, const uint32_t* a, const uint32_t* b) {
    asm volatile(
        "mma.sync.aligned.m16n8k8.row.col.f32.tf32.tf32.f32 "
        "{%0,%1,%2,%3}, {%4,%5,%6,%7}, {%8,%9}, {%0,%1,%2,%3};"
        : "+f"(c[0]), "+f"(c[1]), "+f"(c[2]), "+f"(c[3])
        : "r"(a[0]), "r"(a[1]), "r"(a[2]), "r"(a[3]), "r"(b[0]), "r"(b[1]));
}

#define CP16(dst, src, sz) \
    asm volatile("cp.async.cg.shared.global [%0], [%1], 16, %2;" \
        :: "r"(dst), "l"(src), "r"(sz))
#define CP_COMMIT() asm volatile("cp.async.commit_group;" ::: "memory")
#define CP_WAIT1()  asm volatile("cp.async.wait_group 1;" ::: "memory")

__global__ __launch_bounds__(256, 2)
void k_tc_gemm(const float* __restrict__ A, const float* __restrict__ Bt,
               float* __restrict__ C,
               const float* __restrict__ asrc, const float* __restrict__ adst,
               float* __restrict__ als, float* __restrict__ ald,
               int H, int M, int Nmat, int K)
{
    extern __shared__ uint32_t dynsm[];
    uint32_t* dynA = dynsm;                    // [3][STAGE_WORDS]
    uint32_t* dynB = dynsm + 3 * STAGE_WORDS;  // [3][STAGE_WORDS]
    __shared__ float s_als[128];
    __shared__ float s_ald[128];

    int tid  = threadIdx.x;
    int lane = tid & 31;
    int warp = tid >> 5;
    int warpM = warp >> 1;          // 0..3
    int warpN = warp & 1;           // 0..1
    int g = lane >> 2;              // 0..7
    int t = lane & 3;               // 0..3

    int rowBase = blockIdx.y * 128;
    int colBase = blockIdx.x * 128;

    if (tid < 128) { s_als[tid] = 0.f; s_ald[tid] = 0.f; }

    uint32_t smA = (uint32_t)__cvta_generic_to_shared(dynA);
    uint32_t smB = (uint32_t)__cvta_generic_to_shared(dynB);

    // per-thread tile-copy coords: 2 chunks of 16B per operand per stage
    int r0 = tid >> 2,           c0 = (tid & 3) * 4;
    int r1 = (tid + 256) >> 2,   c1 = ((tid + 256) & 3) * 4;
    int ga0 = rowBase + r0, ga1 = rowBase + r1;
    const float* a0p = A + (size_t)min(ga0, M - 1) * K + c0;
    const float* a1p = A + (size_t)min(ga1, M - 1) * K + c1;
    uint32_t a0sz = (ga0 < M) ? 16 : 0;
    uint32_t a1sz = (ga1 < M) ? 16 : 0;
    const float* b0p = Bt + (size_t)(colBase + r0) * K + c0;
    const float* b1p = Bt + (size_t)(colBase + r1) * K + c1;
    uint32_t ad0 = (uint32_t)(r0 * SAPITCH + c0) << 2;
    uint32_t ad1 = (uint32_t)(r1 * SAPITCH + c1) << 2;

#define ISSUE_TILE(st, k0)                                                     \
    {                                                                          \
        uint32_t sa = smA + (st) * (STAGE_WORDS * 4);                          \
        uint32_t sb = smB + (st) * (STAGE_WORDS * 4);                          \
        CP16(sa + ad0, a0p + (k0), a0sz);                                      \
        CP16(sa + ad1, a1p + (k0), a1sz);                                      \
        CP16(sb + ad0, b0p + (k0), 16u);                                       \
        CP16(sb + ad1, b1p + (k0), 16u);                                       \
    }

    float acc[2][8][4];
#pragma unroll
    for (int i = 0; i < 2; i++)
#pragma unroll
        for (int j = 0; j < 8; j++)
#pragma unroll
            for (int q = 0; q < 4; q++) acc[i][j][q] = 0.f;

    int iters = K >> 4;     // >= 16 for all layers
    ISSUE_TILE(0, 0);  CP_COMMIT();
    ISSUE_TILE(1, 16); CP_COMMIT();

    for (int it = 0; it < iters; it++) {
        CP_WAIT1();
        __syncthreads();
        int cur = it - (it / 3) * 3;
        const uint32_t* sA = dynA + cur * STAGE_WORDS;
        const uint32_t* sB = dynB + cur * STAGE_WORDS;

#pragma unroll
        for (int ks = 0; ks < 16; ks += 8) {
            uint32_t a[2][4], b[8][2];
#pragma unroll
            for (int mt = 0; mt < 2; mt++) {
                int row = warpM * 32 + mt * 16 + g;
                a[mt][0] = sA[row * SAPITCH + ks + t];
                a[mt][1] = sA[(row + 8) * SAPITCH + ks + t];
                a[mt][2] = sA[row * SAPITCH + ks + t + 4];
                a[mt][3] = sA[(row + 8) * SAPITCH + ks + t + 4];
            }
#pragma unroll
            for (int nt = 0; nt < 8; nt++) {
                int col = warpN * 64 + nt * 8 + g;
                b[nt][0] = sB[col * SAPITCH + ks + t];
                b[nt][1] = sB[col * SAPITCH + ks + t + 4];
            }
#pragma unroll
            for (int mt = 0; mt < 2; mt++)
#pragma unroll
                for (int nt = 0; nt < 8; nt++)
                    mma_tf32(acc[mt][nt], a[mt], b[nt]);
        }

        if (it + 2 < iters) {
            int nst = it + 2;
            nst -= (nst / 3) * 3;
            ISSUE_TILE(nst, (it + 2) << 4);
        }
        CP_COMMIT();
    }

    // ---- C store ----
#pragma unroll
    for (int mt = 0; mt < 2; mt++) {
        int row = rowBase + warpM * 32 + mt * 16 + g;
#pragma unroll
        for (int nt = 0; nt < 8; nt++) {
            int col = colBase + warpN * 64 + nt * 8 + 2 * t;
            if (row < M)
                *(float2*)(C + (size_t)row * Nmat + col) =
                    make_float2(acc[mt][nt][0], acc[mt][nt][1]);
            if (row + 8 < M)
                *(float2*)(C + (size_t)(row + 8) * Nmat + col) =
                    make_float2(acc[mt][nt][2], acc[mt][nt][3]);
        }
    }

    // ---- fused attn logits: als/ald for this (row block, head) ----
    {
        int hd = blockIdx.x;                        // colBase / 128
        const float* as = asrc + hd * HID;
        const float* ad = adst + hd * HID;
#pragma unroll
        for (int mt = 0; mt < 2; mt++) {
            float ps0 = 0.f, pd0 = 0.f, ps1 = 0.f, pd1 = 0.f;
#pragma unroll
            for (int nt = 0; nt < 8; nt++) {
                int cih = warpN * 64 + nt * 8 + 2 * t;
                float a0 = as[cih], a1 = as[cih + 1];
                float d0 = ad[cih], d1 = ad[cih + 1];
                ps0 += acc[mt][nt][0] * a0 + acc[mt][nt][1] * a1;
                pd0 += acc[mt][nt][0] * d0 + acc[mt][nt][1] * d1;
                ps1 += acc[mt][nt][2] * a0 + acc[mt][nt][3] * a1;
                pd1 += acc[mt][nt][2] * d0 + acc[mt][nt][3] * d1;
            }
            int rl = warpM * 32 + mt * 16 + g;
            atomicAdd(&s_als[rl], ps0);     atomicAdd(&s_ald[rl], pd0);
            atomicAdd(&s_als[rl + 8], ps1); atomicAdd(&s_ald[rl + 8], pd1);
        }
        __syncthreads();
        if (tid < 128) {
            int row = rowBase + tid;
            if (row < M) {
                als[row * H + hd] = s_als[tid];
                ald[row * H + hd] = s_ald[tid];
            }
        }
    }
#undef ISSUE_TILE
}

// ---------------- fused edge-softmax + aggregate: block=node, warp=head ----------------
__device__ __forceinline__ float leaky02(float x) { return x > 0.f ? x : 0.2f * x; }
__device__ __forceinline__ float eluf(float x)    { return x > 0.f ? x : expm1f(x); }

__device__ __forceinline__ float4 agg_head(const float* __restrict__ h,
                                           const float* __restrict__ als,
                                           float ald, int hd, int H, int D,
                                           int start, int end, int lane)
{
    const float4* h4 = (const float4*)h;
    int rowStride = D >> 2;
    int colOff = hd * 32 + lane;
    float4 acc  = make_float4(0.f, 0.f, 0.f, 0.f);
    float4 acc2 = make_float4(0.f, 0.f, 0.f, 0.f);
    int deg = end - start;

    if (deg <= 32) {
        // fast path: one edge per lane; logit loaded once, kept in-register
        int e = start + lane;
        int s = 0; float el = -1e30f;
        if (e < end) {
            s = g_csr[e];
            el = leaky02(als[s * H + hd] + ald);
        }
        float m = el;
#pragma unroll
        for (int o = 16; o > 0; o >>= 1) m = fmaxf(m, __shfl_xor_sync(0xffffffffu, m, o));
        float w = (e < end) ? __expf(el - m) : 0.f;
        float ssum = w;
#pragma unroll
        for (int o = 16; o > 0; o >>= 1) ssum += __shfl_xor_sync(0xffffffffu, ssum, o);
        w *= 1.f / (ssum + 1e-16f);
#pragma unroll 4
        for (int j = 0; j < deg; j++) {
            int   sj = __shfl_sync(0xffffffffu, s, j);
            float wj = __shfl_sync(0xffffffffu, w, j);
            float4 v = h4[(size_t)sj * rowStride + colOff];
            if (j & 1) {
                acc2.x += wj * v.x; acc2.y += wj * v.y;
                acc2.z += wj * v.z; acc2.w += wj * v.w;
            } else {
                acc.x += wj * v.x; acc.y += wj * v.y;
                acc.z += wj * v.z; acc.w += wj * v.w;
            }
        }
    } else {
        // general path: two-pass softmax
        float m = -1e30f;
        for (int i = start + lane; i < end; i += 32)
            m = fmaxf(m, leaky02(als[g_csr[i] * H + hd] + ald));
#pragma unroll
        for (int o = 16; o > 0; o >>= 1) m = fmaxf(m, __shfl_xor_sync(0xffffffffu, m, o));
        float ssum = 0.f;
        for (int i = start + lane; i < end; i += 32)
            ssum += __expf(leaky02(als[g_csr[i] * H + hd] + ald) - m);
#pragma unroll
        for (int o = 16; o > 0; o >>= 1) ssum += __shfl_xor_sync(0xffffffffu, ssum, o);
        float inv = 1.f / (ssum + 1e-16f);

        for (int base = start; base < end; base += 32) {
            int e = base + lane;
            int s = 0; float w = 0.f;
            if (e < end) {
                s = g_csr[e];
                w = __expf(leaky02(als[s * H + hd] + ald) - m) * inv;
            }
            int cnt = min(32, end - base);
#pragma unroll 4
            for (int j = 0; j < cnt; j++) {
                int   sj = __shfl_sync(0xffffffffu, s, j);
                float wj = __shfl_sync(0xffffffffu, w, j);
                float4 v = h4[(size_t)sj * rowStride + colOff];
                if (j & 1) {
                    acc2.x += wj * v.x; acc2.y += wj * v.y;
                    acc2.z += wj * v.z; acc2.w += wj * v.w;
                } else {
                    acc.x += wj * v.x; acc.y += wj * v.y;
                    acc.z += wj * v.z; acc.w += wj * v.w;
                }
            }
        }
    }
    acc.x += acc2.x; acc.y += acc2.y; acc.z += acc2.z; acc.w += acc2.w;
    return acc;
}

// MODE 1: out = tf32(elu(acc + bias)); MODE 2: out = tf32(elu(resid + acc + bias))
// Outputs tf32-rounded so the next GEMM can cp.async them directly.
template <int MODE>
__global__ void k_agg(const float* __restrict__ h, const float* __restrict__ als,
                      const float* __restrict__ aldp, const float* __restrict__ bias,
                      const float* __restrict__ resid, float* __restrict__ out,
                      int H, int D)
{
    int node = blockIdx.x;
    int hd   = threadIdx.y;
    int lane = threadIdx.x;
    int start = g_offs[node], end = g_offs[node + 1];
    float ald = aldp[node * H + hd];

    float4 acc = agg_head(h, als, ald, hd, H, D, start, end, lane);

    int col = hd * HID + lane * 4;
    const float4 b = *(const float4*)(bias + col);
    float4 o_;
    if (MODE == 1) {
        o_.x = eluf(acc.x + b.x); o_.y = eluf(acc.y + b.y);
        o_.z = eluf(acc.z + b.z); o_.w = eluf(acc.w + b.w);
    } else {
        const float4 r = *(const float4*)(resid + (size_t)node * D + col);
        o_.x = eluf(acc.x + b.x + r.x); o_.y = eluf(acc.y + b.y + r.y);
        o_.z = eluf(acc.z + b.z + r.z); o_.w = eluf(acc.w + b.w + r.w);
    }
    o_.x = __uint_as_float(to_tf32(o_.x)); o_.y = __uint_as_float(to_tf32(o_.y));
    o_.z = __uint_as_float(to_tf32(o_.z)); o_.w = __uint_as_float(to_tf32(o_.w));
    *(float4*)(out + (size_t)node * D + col) = o_;
}

// Layer-3 agg fused with head-mean + bias + global mean pool (atomic into g_pooled)
__global__ void k_agg3(const float* __restrict__ h, const float* __restrict__ als,
                       const float* __restrict__ aldp, const float* __restrict__ b3,
                       const int* __restrict__ batch)
{
    __shared__ float4 sacc[H3N][32];

    int node = blockIdx.x;
    int hd   = threadIdx.y;
    int lane = threadIdx.x;
    int start = g_offs[node], end = g_offs[node + 1];
    float ald = aldp[node * H3N + hd];

    float4 acc = agg_head(h, als, ald, hd, H3N, D3, start, end, lane);
    sacc[hd][lane] = acc;
    __syncthreads();

    if (hd == 0) {
        float4 a0 = sacc[0][lane], a1 = sacc[1][lane], a2 = sacc[2][lane];
        const float4 b = *(const float4*)(b3 + lane * 4);
        float4 v;
        v.x = (a0.x + a1.x + a2.x) * (1.f / 3.f) + b.x;
        v.y = (a0.y + a1.y + a2.y) * (1.f / 3.f) + b.y;
        v.z = (a0.z + a1.z + a2.z) * (1.f / 3.f) + b.z;
        v.w = (a0.w + a1.w + a2.w) * (1.f / 3.f) + b.w;
        int grp = batch[node];
        float* pp = g_pooled + grp * HID + lane * 4;
        atomicAdd(pp + 0, v.x);
        atomicAdd(pp + 1, v.y);
        atomicAdd(pp + 2, v.z);
        atomicAdd(pp + 3, v.w);
        if (lane == 0) atomicAdd(&g_cnt[grp], 1);
    }
}

__global__ void k_classify(const float* __restrict__ Wc, const float* __restrict__ bc,
                           float* __restrict__ out, int out_size)
{
    __shared__ float lg[GG * NCLS];
    __shared__ float rowm[GG], rowl[GG];
    int t = threadIdx.x;            // 640 threads
    int g = t / NCLS, c = t - g * NCLS;
    float cnt = (float)max(g_cnt[g], 1);
    float s = 0.f;
#pragma unroll
    for (int k = 0; k < HID; k++) s += g_pooled[g * HID + k] * Wc[k * NCLS + c];
    float logit = s / cnt + bc[c];
    lg[t] = logit;
    __syncthreads();
    if (t < GG) {
        float m = -1e30f;
        for (int j = 0; j < NCLS; j++) m = fmaxf(m, lg[t * NCLS + j]);
        float se = 0.f;
        for (int j = 0; j < NCLS; j++) se += expf(lg[t * NCLS + j] - m);
        rowm[t] = m; rowl[t] = logf(se);
    }
    __syncthreads();
    out[t] = logit;
    if (out_size >= 2 * GG * NCLS)
        out[GG * NCLS + t] = logit - rowm[g] - rowl[g];
}

// ---------------- launch ----------------
extern "C" void kernel_launch(void* const* d_in, const int* in_sizes, int n_in,
                              void* d_out, int out_size)
{
    const float* x     = (const float*)d_in[0];
    const int*   ei    = (const int*)  d_in[1];
    const int*   batch = (const int*)  d_in[2];
    const float* W1  = (const float*)d_in[3];
    const float* a1s = (const float*)d_in[4];
    const float* a1d = (const float*)d_in[5];
    const float* b1  = (const float*)d_in[6];
    const float* W2  = (const float*)d_in[7];
    const float* a2s = (const float*)d_in[8];
    const float* a2d = (const float*)d_in[9];
    const float* b2  = (const float*)d_in[10];
    const float* W3  = (const float*)d_in[11];
    const float* a3s = (const float*)d_in[12];
    const float* a3d = (const float*)d_in[13];
    const float* b3  = (const float*)d_in[14];
    const float* Wc  = (const float*)d_in[15];
    const float* bc  = (const float*)d_in[16];
    float* out = (float*)d_out;

    float *h_, *x1_, *x2_, *als_, *ald_, *wt1_, *wt2_, *wt3_;
    cudaGetSymbolAddress((void**)&h_,  g_h);
    cudaGetSymbolAddress((void**)&x1_, g_x1);
    cudaGetSymbolAddress((void**)&x2_, g_x2);
    cudaGetSymbolAddress((void**)&als_, g_als);
    cudaGetSymbolAddress((void**)&ald_, g_ald);
    cudaGetSymbolAddress((void**)&wt1_, g_Wt1);
    cudaGetSymbolAddress((void**)&wt2_, g_Wt2);
    cudaGetSymbolAddress((void**)&wt3_, g_Wt3);

    cudaFuncSetAttribute(k_tc_gemm, cudaFuncAttributeMaxDynamicSharedMemorySize,
                         GEMM_DYN_SMEM);

    dim3 tb(32, 8);

    // Slots 0-2 (keep gemm1 at profiled slot 3)
    k_zero<<<(NN + 255) / 256, 256>>>();                                   // 0
    k_transpose_all<<<dim3(D1 / 32, D1 / 32, 3), tb>>>(W1, W2, W3);        // 1
    k_round<<<(NN * FIN / 4 + 255) / 256, 256>>>(x, x2_, NN * FIN / 4);    // 2 (x2_ scratch)

    // Layer-1 GEMM (+fused attn)                                          // 3
    k_tc_gemm<<<dim3(D1 / 128, (NN + 127) / 128), 256, GEMM_DYN_SMEM>>>(
        x2_, wt1_, h_, a1s, a1d, als_, ald_, H1N, NN, D1, FIN);

    // CSR by dst
    k_count  <<<(ET + 255) / 256, 256>>>(ei);
    k_scan   <<<1, 1024>>>();
    k_scatter<<<(ET + 255) / 256, 256>>>(ei);

    // Layer 1 aggregate (emits tf32-rounded x1)
    k_agg<1><<<NN, dim3(32, H1N)>>>(h_, als_, ald_, b1, nullptr, x1_, H1N, D1);

    // Layer 2 (residual; emits tf32-rounded x2 — scratch reuse is done by now)
    k_tc_gemm<<<dim3(D1 / 128, (NN + 127) / 128), 256, GEMM_DYN_SMEM>>>(
        x1_, wt2_, h_, a2s, a2d, als_, ald_, H1N, NN, D1, D1);
    k_agg<2><<<NN, dim3(32, H1N)>>>(h_, als_, ald_, b2, x1_, x2_, H1N, D1);

    // Layer 3 (head mean + pool fused)
    k_tc_gemm<<<dim3(D3 / 128, (NN + 127) / 128), 256, GEMM_DYN_SMEM>>>(
        x2_, wt3_, h_, a3s, a3d, als_, ald_, H3N, NN, D3, D1);
    k_agg3<<<NN, dim3(32, H3N)>>>(h_, als_, ald_, b3, batch);

    // Classify
    k_classify<<<1, GG * NCLS>>>(Wc, bc, out, out_size);
}